// round 2
// baseline (speedup 1.0000x reference)
#include <cuda_runtime.h>
#include <cuda_bf16.h>
#include <math.h>

#define NCELLS 16384
#define DMODEL 768
#define MAXH   8
#define NHEADS 8
#define DHEAD  96
#define NHDR   512

// ---------------- scratch (static device allocations are allowed) ----------
__device__ float g_cwp[NCELLS * DMODEL];   // cell + pos emb
__device__ float g_q  [NCELLS * DMODEL];   // Q projection
__device__ float g_ctx[NCELLS * DMODEL];   // attention context
__device__ float g_att[NCELLS * DMODEL];   // out-proj result
__device__ float g_h  [NCELLS * DMODEL];   // fusion pre-LN
__device__ float g_K  [NHDR * DMODEL];     // projected header keys
__device__ float g_V  [NHDR * DMODEL];     // projected header values

// ---------------- cwp = cell + row_emb[r] + col_emb[c] ---------------------
__global__ void cwp_kernel(const float* __restrict__ cell,
                           const int*   __restrict__ pos,
                           const float* __restrict__ rowe,
                           const float* __restrict__ cole) {
    int idx = blockIdx.x * blockDim.x + threadIdx.x;          // float4 index
    int n   = idx / (DMODEL / 4);
    int d4  = idx % (DMODEL / 4);
    if (n >= NCELLS) return;
    int r = pos[n * 2 + 0]; r = r < 0 ? 0 : (r > 99 ? 99 : r);
    int c = pos[n * 2 + 1]; c = c < 0 ? 0 : (c > 99 ? 99 : c);
    const float4 cv = ((const float4*)cell)[(size_t)n * (DMODEL/4) + d4];
    const float4 rv = ((const float4*)rowe)[(size_t)r * (DMODEL/4) + d4];
    const float4 lv = ((const float4*)cole)[(size_t)c * (DMODEL/4) + d4];
    float4 o;
    o.x = cv.x + rv.x + lv.x; o.y = cv.y + rv.y + lv.y;
    o.z = cv.z + rv.z + lv.z; o.w = cv.w + rv.w + lv.w;
    ((float4*)g_cwp)[(size_t)n * (DMODEL/4) + d4] = o;
}

// ---------------- NT GEMM:  C[m][o] = sum_k A[m][k]*B[o][k] (+part2) + bias -
// N (out cols) fixed at 768, K per part fixed at 768. A2 may be null (1 part).
// B row o: part p occupies B[o*ldb + p*768 + k].
#define BM 128
#define BN 128
#define BK 8
__global__ __launch_bounds__(256, 2)
void gemm_nt(const float* __restrict__ A1, const float* __restrict__ A2,
             const float* __restrict__ B, int ldb,
             const float* __restrict__ bias, float* __restrict__ C, int M) {
    __shared__ float As[BK][BM];
    __shared__ float Bs[BK][BN];
    const int bm = blockIdx.x * BM;
    const int bn = blockIdx.y * BN;
    const int tid = threadIdx.x;
    const int tx = tid & 15, ty = tid >> 4;
    const int lrow = tid >> 1;
    const int lcol = (tid & 1) * 4;

    float acc[8][8];
#pragma unroll
    for (int i = 0; i < 8; i++)
#pragma unroll
        for (int j = 0; j < 8; j++) acc[i][j] = 0.f;

    const int nparts = A2 ? 2 : 1;
    for (int p = 0; p < nparts; ++p) {
        const float* A = p ? A2 : A1;
        const int koff = p * 768;
        for (int k0 = 0; k0 < 768; k0 += BK) {
            float4 av = *(const float4*)(A + (size_t)(bm + lrow) * 768 + k0 + lcol);
            float4 bv = *(const float4*)(B + (size_t)(bn + lrow) * ldb + koff + k0 + lcol);
            __syncthreads();
            As[lcol + 0][lrow] = av.x; As[lcol + 1][lrow] = av.y;
            As[lcol + 2][lrow] = av.z; As[lcol + 3][lrow] = av.w;
            Bs[lcol + 0][lrow] = bv.x; Bs[lcol + 1][lrow] = bv.y;
            Bs[lcol + 2][lrow] = bv.z; Bs[lcol + 3][lrow] = bv.w;
            __syncthreads();
#pragma unroll
            for (int kk = 0; kk < BK; kk++) {
                float a[8], bf[8];
                *(float4*)&a[0]  = *(const float4*)&As[kk][ty * 4];
                *(float4*)&a[4]  = *(const float4*)&As[kk][64 + ty * 4];
                *(float4*)&bf[0] = *(const float4*)&Bs[kk][tx * 4];
                *(float4*)&bf[4] = *(const float4*)&Bs[kk][64 + tx * 4];
#pragma unroll
                for (int i = 0; i < 8; i++)
#pragma unroll
                    for (int j = 0; j < 8; j++) acc[i][j] += a[i] * bf[j];
            }
        }
    }
#pragma unroll
    for (int i = 0; i < 8; i++) {
        int rl = (i < 4) ? (ty * 4 + i) : (64 + ty * 4 + i - 4);
        int row = bm + rl;
#pragma unroll
        for (int j = 0; j < 8; j++) {
            int cl = (j < 4) ? (tx * 4 + j) : (64 + tx * 4 + j - 4);
            int col = bn + cl;
            C[(size_t)row * 768 + col] = acc[i][j] + bias[col];
        }
    }
}

// ---------------- attention: one warp per cell -----------------------------
__global__ void attn_kernel(const int* __restrict__ map, float* __restrict__ wout) {
    const int gw = (blockIdx.x * blockDim.x + threadIdx.x) >> 5;
    const int lane = threadIdx.x & 31;
    if (gw >= NCELLS) return;
    const int n = gw;
    const int myh = lane >> 2;      // header slot handled by this lane group
    const int s = lane & 3;         // sub-reduction index
    const unsigned FULL = 0xffffffffu;

    int id = 0, vld = 0;
    if (lane < MAXH) {
        id = map[n * MAXH + lane];
        vld = (id >= 0);
        if (!vld) id = 0;
    }
    int idh[MAXH];
    unsigned vmask = 0;
#pragma unroll
    for (int h = 0; h < MAXH; h++) {
        idh[h] = __shfl_sync(FULL, id, h);
        if (__shfl_sync(FULL, vld, h)) vmask |= (1u << h);
    }
    const bool myvalid = (vmask >> myh) & 1;
    const float scale = 0.1020620726159658f;  // 1/sqrt(96)

    float attn_l[NHEADS];
    float wacc = 0.f;
#pragma unroll
    for (int a = 0; a < NHEADS; a++) {
        const float* qa = g_q + (size_t)n * DMODEL + a * DHEAD;
        const float* ka = g_K + (size_t)idh[myh] * DMODEL + a * DHEAD;
        float part = 0.f;
#pragma unroll
        for (int j = 0; j < 24; j++) part += qa[s * 24 + j] * ka[s * 24 + j];
        part += __shfl_xor_sync(FULL, part, 1);
        part += __shfl_xor_sync(FULL, part, 2);
        float sc = myvalid ? part * scale : -1e9f;
        float m = sc;
        m = fmaxf(m, __shfl_xor_sync(FULL, m, 4));
        m = fmaxf(m, __shfl_xor_sync(FULL, m, 8));
        m = fmaxf(m, __shfl_xor_sync(FULL, m, 16));
        float e = __expf(sc - m);
        float ssum = e;
        ssum += __shfl_xor_sync(FULL, ssum, 4);
        ssum += __shfl_xor_sync(FULL, ssum, 8);
        ssum += __shfl_xor_sync(FULL, ssum, 16);
        float at = myvalid ? (e / ssum) : 0.f;
        attn_l[a] = at;
        wacc += at;
    }
    if (s == 0) wout[(size_t)n * MAXH + myh] = wacc * 0.125f;

    // ctx[a][j] = sum_h attn[a][h] * V[id_h][a*96 + j]
#pragma unroll
    for (int a = 0; a < NHEADS; a++) {
        float c0 = 0.f, c1 = 0.f, c2 = 0.f;
#pragma unroll
        for (int h = 0; h < MAXH; h++) {
            float ah = __shfl_sync(FULL, attn_l[a], h << 2);
            const float* va = g_V + (size_t)idh[h] * DMODEL + a * DHEAD;
            c0 += ah * va[lane];
            c1 += ah * va[lane + 32];
            c2 += ah * va[lane + 64];
        }
        float* cp = g_ctx + (size_t)n * DMODEL + a * DHEAD;
        cp[lane] = c0; cp[lane + 32] = c1; cp[lane + 64] = c2;
    }
}

// ---------------- LayerNorm + ReLU + select: one warp per row --------------
__global__ void ln_kernel(const int* __restrict__ map,
                          const float* __restrict__ gam,
                          const float* __restrict__ bet,
                          float* __restrict__ out) {
    const int gw = (blockIdx.x * blockDim.x + threadIdx.x) >> 5;
    const int lane = threadIdx.x & 31;
    if (gw >= NCELLS) return;
    const int n = gw;
    const unsigned FULL = 0xffffffffu;
    const float* hr = g_h + (size_t)n * DMODEL;

    float v[24];
    float sum = 0.f;
#pragma unroll
    for (int k = 0; k < 24; k++) { v[k] = hr[lane + k * 32]; sum += v[k]; }
#pragma unroll
    for (int o = 16; o > 0; o >>= 1) sum += __shfl_xor_sync(FULL, sum, o);
    const float mu = sum * (1.0f / 768.0f);
    float var = 0.f;
#pragma unroll
    for (int k = 0; k < 24; k++) { float d = v[k] - mu; var += d * d; }
#pragma unroll
    for (int o = 16; o > 0; o >>= 1) var += __shfl_xor_sync(FULL, var, o);
    var *= (1.0f / 768.0f);
    const float r = rsqrtf(var + 1e-5f);

    bool anyv = false;
    if (lane < MAXH) anyv = (map[n * MAXH + lane] >= 0);
    anyv = __any_sync(FULL, anyv);

    const float* cr = g_cwp + (size_t)n * DMODEL;
#pragma unroll
    for (int k = 0; k < 24; k++) {
        int d = lane + k * 32;
        float val = (v[k] - mu) * r * gam[d] + bet[d];
        val = fmaxf(val, 0.f);
        out[(size_t)n * DMODEL + d] = anyv ? val : cr[d];
    }
}

// ---------------- launch ----------------------------------------------------
extern "C" void kernel_launch(void* const* d_in, const int* in_sizes, int n_in,
                              void* d_out, int out_size) {
    const float* cell   = (const float*)d_in[0];
    const float* hdr    = (const float*)d_in[1];
    const int*   map    = (const int*)  d_in[2];
    const int*   pos    = (const int*)  d_in[3];
    const float* inw    = (const float*)d_in[4];   // [2304,768]: Wq,Wk,Wv
    const float* inb    = (const float*)d_in[5];   // [2304]
    const float* outw   = (const float*)d_in[6];
    const float* outb   = (const float*)d_in[7];
    const float* rowe   = (const float*)d_in[8];
    const float* cole   = (const float*)d_in[9];
    const float* fusw   = (const float*)d_in[10];  // [768,1536]
    const float* fusb   = (const float*)d_in[11];
    const float* lng    = (const float*)d_in[12];
    const float* lnb    = (const float*)d_in[13];
    float* out = (float*)d_out;
    float* wout = out + (size_t)NCELLS * DMODEL;   // weights after enriched

    float *cwp, *q, *ctx, *att, *h, *K, *V;
    cudaGetSymbolAddress((void**)&cwp, g_cwp);
    cudaGetSymbolAddress((void**)&q,   g_q);
    cudaGetSymbolAddress((void**)&ctx, g_ctx);
    cudaGetSymbolAddress((void**)&att, g_att);
    cudaGetSymbolAddress((void**)&h,   g_h);
    cudaGetSymbolAddress((void**)&K,   g_K);
    cudaGetSymbolAddress((void**)&V,   g_V);

    // 1. cwp
    {
        int total = NCELLS * (DMODEL / 4);
        cwp_kernel<<<(total + 255) / 256, 256>>>(cell, pos, rowe, cole);
    }
    // 2. header K/V projections (512 rows only!)
    {
        dim3 grid(NHDR / BM, DMODEL / BN);
        gemm_nt<<<grid, 256>>>(hdr, nullptr, inw + 768 * 768, 768, inb + 768,  K, NHDR);
        gemm_nt<<<grid, 256>>>(hdr, nullptr, inw + 2 * 768 * 768, 768, inb + 1536, V, NHDR);
    }
    // 3. Q projection
    {
        dim3 grid(NCELLS / BM, DMODEL / BN);
        gemm_nt<<<grid, 256>>>(cwp, nullptr, inw, 768, inb, q, NCELLS);
    }
    // 4. attention (one warp per cell)
    attn_kernel<<<(NCELLS * 32 + 255) / 256, 256>>>(map, wout);
    // 5. out projection
    {
        dim3 grid(NCELLS / BM, DMODEL / BN);
        gemm_nt<<<grid, 256>>>(ctx, nullptr, outw, 768, outb, att, NCELLS);
    }
    // 6. fusion: h = [cwp, att] @ fus_w^T + fus_b
    {
        dim3 grid(NCELLS / BM, DMODEL / BN);
        gemm_nt<<<grid, 256>>>(cwp, att, fusw, 1536, fusb, h, NCELLS);
    }
    // 7. LayerNorm + ReLU + select
    ln_kernel<<<(NCELLS * 32 + 255) / 256, 256>>>(map, lng, lnb, out);
}

// round 5
// speedup vs baseline: 1.8314x; 1.8314x over previous
#include <cuda_runtime.h>
#include <cuda_bf16.h>
#include <cstdint>
#include <math.h>

#define NCELLS 16384
#define DMODEL 768
#define MAXH   8
#define NHEADS 8
#define DHEAD  96
#define NHDR   512

// ---------------- scratch ---------------------------------------------------
__device__ float g_cwp[NCELLS * DMODEL];
__device__ float g_q  [NCELLS * DMODEL];
__device__ float g_ctx[NCELLS * DMODEL];
__device__ float g_att[NCELLS * DMODEL];
__device__ float g_h  [NCELLS * DMODEL];
__device__ float g_K  [NHDR * DMODEL];
__device__ float g_V  [NHDR * DMODEL];
__device__ __nv_bfloat16 g_Abig[(size_t)NCELLS * 4608];  // split-bf16 A operand
__device__ __nv_bfloat16 g_Bbig[(size_t)DMODEL * 4608];  // split-bf16 B operand

// ---------------- PTX helpers (baseline PTX only: sm_80-class) -------------
__device__ __forceinline__ uint32_t smem_u32(const void* p) {
    uint32_t a;
    asm("{ .reg .u64 t; cvta.to.shared.u64 t, %1; cvt.u32.u64 %0, t; }" : "=r"(a) : "l"(p));
    return a;
}
__device__ __forceinline__ void cp16(uint32_t dst, const void* src) {
    asm volatile("cp.async.cg.shared.global [%0], [%1], 16;" :: "r"(dst), "l"(src));
}
__device__ __forceinline__ void ldsm4(uint32_t& r0, uint32_t& r1, uint32_t& r2, uint32_t& r3,
                                      uint32_t addr) {
    asm volatile("ldmatrix.sync.aligned.m8n8.x4.shared.b16 {%0,%1,%2,%3}, [%4];"
                 : "=r"(r0), "=r"(r1), "=r"(r2), "=r"(r3) : "r"(addr));
}
__device__ __forceinline__ void mma16816(float* d, const uint32_t* a, const uint32_t* b) {
    asm volatile("mma.sync.aligned.m16n8k16.row.col.f32.bf16.bf16.f32 "
                 "{%0,%1,%2,%3},{%4,%5,%6,%7},{%8,%9},{%0,%1,%2,%3};"
                 : "+f"(d[0]), "+f"(d[1]), "+f"(d[2]), "+f"(d[3])
                 : "r"(a[0]), "r"(a[1]), "r"(a[2]), "r"(a[3]), "r"(b[0]), "r"(b[1]));
}

// ---------------- cwp = cell + row_emb[r] + col_emb[c] ---------------------
__global__ void cwp_kernel(const float* __restrict__ cell,
                           const int*   __restrict__ pos,
                           const float* __restrict__ rowe,
                           const float* __restrict__ cole) {
    int idx = blockIdx.x * blockDim.x + threadIdx.x;
    int n   = idx / (DMODEL / 4);
    int d4  = idx % (DMODEL / 4);
    if (n >= NCELLS) return;
    int r = pos[n * 2 + 0]; r = r < 0 ? 0 : (r > 99 ? 99 : r);
    int c = pos[n * 2 + 1]; c = c < 0 ? 0 : (c > 99 ? 99 : c);
    const float4 cv = ((const float4*)cell)[(size_t)n * (DMODEL/4) + d4];
    const float4 rv = ((const float4*)rowe)[(size_t)r * (DMODEL/4) + d4];
    const float4 lv = ((const float4*)cole)[(size_t)c * (DMODEL/4) + d4];
    float4 o;
    o.x = cv.x + rv.x + lv.x; o.y = cv.y + rv.y + lv.y;
    o.z = cv.z + rv.z + lv.z; o.w = cv.w + rv.w + lv.w;
    ((float4*)g_cwp)[(size_t)n * (DMODEL/4) + d4] = o;
}

// ---------------- split-bf16 conversion ------------------------------------
// A' row = [hi(ncol) | hi(ncol) | lo(ncol)], sources X1 (cols 0..767), X2 (768..1535)
__global__ void splitA(const float* __restrict__ X1, const float* __restrict__ X2,
                       int ncol, __nv_bfloat16* __restrict__ out) {
    int idx = blockIdx.x * blockDim.x + threadIdx.x;
    int per = ncol >> 2;
    int m = idx / per, k4 = idx % per;
    if (m >= NCELLS) return;
    int k = k4 * 4;
    const float* src = (k < 768) ? (X1 + (size_t)m * 768 + k)
                                 : (X2 + (size_t)m * 768 + (k - 768));
    float4 x = *(const float4*)src;
    __nv_bfloat16 h0 = __float2bfloat16_rn(x.x), h1 = __float2bfloat16_rn(x.y);
    __nv_bfloat16 h2 = __float2bfloat16_rn(x.z), h3 = __float2bfloat16_rn(x.w);
    __nv_bfloat16 l0 = __float2bfloat16_rn(x.x - __bfloat162float(h0));
    __nv_bfloat16 l1 = __float2bfloat16_rn(x.y - __bfloat162float(h1));
    __nv_bfloat16 l2 = __float2bfloat16_rn(x.z - __bfloat162float(h2));
    __nv_bfloat16 l3 = __float2bfloat16_rn(x.w - __bfloat162float(h3));
    __nv_bfloat162 hA(h0, h1), hB(h2, h3), lA(l0, l1), lB(l2, l3);
    size_t base = (size_t)m * (3 * ncol);
    __nv_bfloat162* o0 = (__nv_bfloat162*)(out + base + k);
    __nv_bfloat162* o1 = (__nv_bfloat162*)(out + base + ncol + k);
    __nv_bfloat162* o2 = (__nv_bfloat162*)(out + base + 2 * ncol + k);
    o0[0] = hA; o0[1] = hB;
    o1[0] = hA; o1[1] = hB;
    o2[0] = lA; o2[1] = lB;
}
// B' row = [hi(ncol) | lo(ncol) | hi(ncol)], W is [768, ncol]
__global__ void splitB(const float* __restrict__ W, int ncol,
                       __nv_bfloat16* __restrict__ out) {
    int idx = blockIdx.x * blockDim.x + threadIdx.x;
    int per = ncol >> 2;
    int m = idx / per, k4 = idx % per;
    if (m >= DMODEL) return;
    int k = k4 * 4;
    float4 x = *(const float4*)(W + (size_t)m * ncol + k);
    __nv_bfloat16 h0 = __float2bfloat16_rn(x.x), h1 = __float2bfloat16_rn(x.y);
    __nv_bfloat16 h2 = __float2bfloat16_rn(x.z), h3 = __float2bfloat16_rn(x.w);
    __nv_bfloat16 l0 = __float2bfloat16_rn(x.x - __bfloat162float(h0));
    __nv_bfloat16 l1 = __float2bfloat16_rn(x.y - __bfloat162float(h1));
    __nv_bfloat16 l2 = __float2bfloat16_rn(x.z - __bfloat162float(h2));
    __nv_bfloat16 l3 = __float2bfloat16_rn(x.w - __bfloat162float(h3));
    __nv_bfloat162 hA(h0, h1), hB(h2, h3), lA(l0, l1), lB(l2, l3);
    size_t base = (size_t)m * (3 * ncol);
    __nv_bfloat162* o0 = (__nv_bfloat162*)(out + base + k);
    __nv_bfloat162* o1 = (__nv_bfloat162*)(out + base + ncol + k);
    __nv_bfloat162* o2 = (__nv_bfloat162*)(out + base + 2 * ncol + k);
    o0[0] = hA; o0[1] = hB;
    o1[0] = lA; o1[1] = lB;
    o2[0] = hA; o2[1] = hB;
}

// ---------------- HMMA bf16 NT GEMM: C[M,768] = A'[M,Kp] * B'[768,Kp]^T ----
// CTA tile 128x128; 8 warps in 2(M)x4(N); warp tile 64x32; K chunk 64 bf16.
// 4-stage cp.async pipeline; SW128 swizzled 128B rows; ldmatrix fragments.
#define MM_STAGES 4
#define MM_TB     16384   // one stage of one operand: 128 rows * 128 B

__device__ __forceinline__ void mm_load_chunk(uint32_t sA, uint32_t sB,
                                              const __nv_bfloat16* A,
                                              const __nv_bfloat16* B,
                                              int Kp, int c, int bm, int bn, int tid) {
    const __nv_bfloat16* Ab = A + (size_t)bm * Kp + c * 64;
#pragma unroll
    for (int u = tid; u < 1024; u += 256) {
        int row = u >> 3, seg = u & 7;
        uint32_t off = row * 128 + seg * 16;
        uint32_t sw  = off ^ ((off >> 3) & 0x70);
        cp16(sA + sw, Ab + (size_t)row * Kp + seg * 8);
    }
    const __nv_bfloat16* Bb = B + (size_t)bn * Kp + c * 64;
#pragma unroll
    for (int u = tid; u < 1024; u += 256) {
        int row = u >> 3, seg = u & 7;
        uint32_t off = row * 128 + seg * 16;
        uint32_t sw  = off ^ ((off >> 3) & 0x70);
        cp16(sB + sw, Bb + (size_t)row * Kp + seg * 8);
    }
    asm volatile("cp.async.commit_group;" ::: "memory");
}

__global__ void __launch_bounds__(256, 1)
gemm_mma(const __nv_bfloat16* __restrict__ A, const __nv_bfloat16* __restrict__ B,
         const float* __restrict__ bias, float* __restrict__ C, int Kp) {
    extern __shared__ char smem[];
    const uint32_t sA0 = smem_u32(smem);
    const uint32_t sB0 = sA0 + MM_STAGES * MM_TB;
    const int tid = threadIdx.x, wid = tid >> 5, lane = tid & 31;
    const int bm = blockIdx.x * 128, bn = blockIdx.y * 128;
    const int warp_m = wid & 1, warp_n = wid >> 1;
    const int m0w = warp_m * 64, n0w = warp_n * 32;
    const int nch = Kp >> 6;

    float acc[4][4][4];
#pragma unroll
    for (int i = 0; i < 4; i++)
#pragma unroll
        for (int j = 0; j < 4; j++)
#pragma unroll
            for (int r = 0; r < 4; r++) acc[i][j][r] = 0.f;

    // precomputed swizzled ldmatrix lane addresses (within a stage, ks=0)
    //   A frag (m16k16): row = m0 + (lane&15), bytecol = (lane>>4)*16
    //   B frag (n16k16): row = n0 + (lane&7) + ((lane>>4)<<3), bytecol = ((lane>>3)&1)*16
    uint32_t aoff[4], boff[2];
#pragma unroll
    for (int mi = 0; mi < 4; mi++) {
        uint32_t off = (uint32_t)(m0w + mi * 16 + (lane & 15)) * 128 + (lane >> 4) * 16;
        aoff[mi] = off ^ ((off >> 3) & 0x70);
    }
#pragma unroll
    for (int np = 0; np < 2; np++) {
        uint32_t off = (uint32_t)(n0w + np * 16 + (lane & 7) + ((lane >> 4) << 3)) * 128 +
                       ((lane >> 3) & 1) * 16;
        boff[np] = off ^ ((off >> 3) & 0x70);
    }

    // prologue: stages 0..2
    for (int c = 0; c < MM_STAGES - 1 && c < nch; c++)
        mm_load_chunk(sA0 + c * MM_TB, sB0 + c * MM_TB, A, B, Kp, c, bm, bn, tid);

    for (int c = 0; c < nch; c++) {
        const int s = c & (MM_STAGES - 1);
        asm volatile("cp.async.wait_group 2;" ::: "memory");
        __syncthreads();
        const int cp = c + MM_STAGES - 1;
        if (cp < nch) {
            const int sp = cp & (MM_STAGES - 1);
            mm_load_chunk(sA0 + sp * MM_TB, sB0 + sp * MM_TB, A, B, Kp, cp, bm, bn, tid);
        }
        const uint32_t aBase = sA0 + s * MM_TB;
        const uint32_t bBase = sB0 + s * MM_TB;
#pragma unroll
        for (int ks = 0; ks < 4; ks++) {
            uint32_t a[4][4], b[2][4];
#pragma unroll
            for (int mi = 0; mi < 4; mi++) {
                // ks advances bytecol by 32; swizzle XOR bits are [6:4] from
                // (off>>3)&0x70 — bytecol bits 5..6 feed the XOR, so recompute:
                uint32_t off = aoff[mi] ^ 0;  // base has bytecol bits folded already
                // add ks*32 in un-swizzled space: since row part is fixed, and
                // swizzle = off ^ ((off>>3)&0x70) is an involution affecting only
                // bits 4..6, recompute from scratch to stay safe:
                (void)off;
                uint32_t raw = (uint32_t)(m0w + mi * 16 + (lane & 15)) * 128 +
                               ks * 32 + (lane >> 4) * 16;
                uint32_t sw = raw ^ ((raw >> 3) & 0x70);
                ldsm4(a[mi][0], a[mi][1], a[mi][2], a[mi][3], aBase + sw);
            }
#pragma unroll
            for (int np = 0; np < 2; np++) {
                uint32_t raw = (uint32_t)(n0w + np * 16 + (lane & 7) + ((lane >> 4) << 3)) * 128 +
                               ks * 32 + ((lane >> 3) & 1) * 16;
                uint32_t sw = raw ^ ((raw >> 3) & 0x70);
                ldsm4(b[np][0], b[np][1], b[np][2], b[np][3], bBase + sw);
            }
#pragma unroll
            for (int mi = 0; mi < 4; mi++)
#pragma unroll
                for (int nj = 0; nj < 4; nj++)
                    mma16816(acc[mi][nj], a[mi], &b[nj >> 1][(nj & 1) * 2]);
        }
    }

    // epilogue: bias add + direct gmem store
#pragma unroll
    for (int mi = 0; mi < 4; mi++) {
        const int row0 = bm + m0w + mi * 16 + (lane >> 2);
#pragma unroll
        for (int nj = 0; nj < 4; nj++) {
            const int col = bn + n0w + nj * 8 + (lane & 3) * 2;
            const float b0 = bias[col], b1 = bias[col + 1];
            float2 v0 = make_float2(acc[mi][nj][0] + b0, acc[mi][nj][1] + b1);
            float2 v1 = make_float2(acc[mi][nj][2] + b0, acc[mi][nj][3] + b1);
            *(float2*)(C + (size_t)row0 * 768 + col)       = v0;
            *(float2*)(C + (size_t)(row0 + 8) * 768 + col) = v1;
        }
    }
}

// ---------------- small FFMA NT GEMM (K/V projections, M=512) --------------
#define BM 128
#define BN 128
#define BK 8
__global__ __launch_bounds__(256, 2)
void gemm_nt(const float* __restrict__ A1, const float* __restrict__ A2,
             const float* __restrict__ B, int ldb,
             const float* __restrict__ bias, float* __restrict__ C, int M) {
    __shared__ float As[BK][BM];
    __shared__ float Bs[BK][BN];
    const int bm = blockIdx.x * BM;
    const int bn = blockIdx.y * BN;
    const int tid = threadIdx.x;
    const int tx = tid & 15, ty = tid >> 4;
    const int lrow = tid >> 1;
    const int lcol = (tid & 1) * 4;

    float acc[8][8];
#pragma unroll
    for (int i = 0; i < 8; i++)
#pragma unroll
        for (int j = 0; j < 8; j++) acc[i][j] = 0.f;

    const int nparts = A2 ? 2 : 1;
    for (int p = 0; p < nparts; ++p) {
        const float* A = p ? A2 : A1;
        const int koff = p * 768;
        for (int k0 = 0; k0 < 768; k0 += BK) {
            float4 av = *(const float4*)(A + (size_t)(bm + lrow) * 768 + k0 + lcol);
            float4 bv = *(const float4*)(B + (size_t)(bn + lrow) * ldb + koff + k0 + lcol);
            __syncthreads();
            As[lcol + 0][lrow] = av.x; As[lcol + 1][lrow] = av.y;
            As[lcol + 2][lrow] = av.z; As[lcol + 3][lrow] = av.w;
            Bs[lcol + 0][lrow] = bv.x; Bs[lcol + 1][lrow] = bv.y;
            Bs[lcol + 2][lrow] = bv.z; Bs[lcol + 3][lrow] = bv.w;
            __syncthreads();
#pragma unroll
            for (int kk = 0; kk < BK; kk++) {
                float a[8], bf[8];
                *(float4*)&a[0]  = *(const float4*)&As[kk][ty * 4];
                *(float4*)&a[4]  = *(const float4*)&As[kk][64 + ty * 4];
                *(float4*)&bf[0] = *(const float4*)&Bs[kk][tx * 4];
                *(float4*)&bf[4] = *(const float4*)&Bs[kk][64 + tx * 4];
#pragma unroll
                for (int i = 0; i < 8; i++)
#pragma unroll
                    for (int j = 0; j < 8; j++) acc[i][j] += a[i] * bf[j];
            }
        }
    }
#pragma unroll
    for (int i = 0; i < 8; i++) {
        int rl = (i < 4) ? (ty * 4 + i) : (64 + ty * 4 + i - 4);
        int row = bm + rl;
#pragma unroll
        for (int j = 0; j < 8; j++) {
            int cl = (j < 4) ? (tx * 4 + j) : (64 + tx * 4 + j - 4);
            int col = bn + cl;
            C[(size_t)row * 768 + col] = acc[i][j] + bias[col];
        }
    }
}

// ---------------- attention: one warp per cell -----------------------------
__global__ void attn_kernel(const int* __restrict__ map, float* __restrict__ wout) {
    const int gw = (blockIdx.x * blockDim.x + threadIdx.x) >> 5;
    const int lane = threadIdx.x & 31;
    if (gw >= NCELLS) return;
    const int n = gw;
    const int myh = lane >> 2;
    const int s = lane & 3;
    const unsigned FULL = 0xffffffffu;

    int id = 0, vld = 0;
    if (lane < MAXH) {
        id = map[n * MAXH + lane];
        vld = (id >= 0);
        if (!vld) id = 0;
    }
    int idh[MAXH];
    unsigned vmask = 0;
#pragma unroll
    for (int h = 0; h < MAXH; h++) {
        idh[h] = __shfl_sync(FULL, id, h);
        if (__shfl_sync(FULL, vld, h)) vmask |= (1u << h);
    }
    const bool myvalid = (vmask >> myh) & 1;
    const float scale = 0.1020620726159658f;

    float attn_l[NHEADS];
    float wacc = 0.f;
#pragma unroll
    for (int a = 0; a < NHEADS; a++) {
        const float* qa = g_q + (size_t)n * DMODEL + a * DHEAD;
        const float* ka = g_K + (size_t)idh[myh] * DMODEL + a * DHEAD;
        float part = 0.f;
#pragma unroll
        for (int j = 0; j < 24; j++) part += qa[s * 24 + j] * ka[s * 24 + j];
        part += __shfl_xor_sync(FULL, part, 1);
        part += __shfl_xor_sync(FULL, part, 2);
        float sc = myvalid ? part * scale : -1e9f;
        float m = sc;
        m = fmaxf(m, __shfl_xor_sync(FULL, m, 4));
        m = fmaxf(m, __shfl_xor_sync(FULL, m, 8));
        m = fmaxf(m, __shfl_xor_sync(FULL, m, 16));
        float e = __expf(sc - m);
        float ssum = e;
        ssum += __shfl_xor_sync(FULL, ssum, 4);
        ssum += __shfl_xor_sync(FULL, ssum, 8);
        ssum += __shfl_xor_sync(FULL, ssum, 16);
        float at = myvalid ? (e / ssum) : 0.f;
        attn_l[a] = at;
        wacc += at;
    }
    if (s == 0) wout[(size_t)n * MAXH + myh] = wacc * 0.125f;

#pragma unroll
    for (int a = 0; a < NHEADS; a++) {
        float c0 = 0.f, c1 = 0.f, c2 = 0.f;
#pragma unroll
        for (int h = 0; h < MAXH; h++) {
            float ah = __shfl_sync(FULL, attn_l[a], h << 2);
            const float* va = g_V + (size_t)idh[h] * DMODEL + a * DHEAD;
            c0 += ah * va[lane];
            c1 += ah * va[lane + 32];
            c2 += ah * va[lane + 64];
        }
        float* cp = g_ctx + (size_t)n * DMODEL + a * DHEAD;
        cp[lane] = c0; cp[lane + 32] = c1; cp[lane + 64] = c2;
    }
}

// ---------------- LayerNorm + ReLU + select --------------------------------
__global__ void ln_kernel(const int* __restrict__ map,
                          const float* __restrict__ gam,
                          const float* __restrict__ bet,
                          float* __restrict__ out) {
    const int gw = (blockIdx.x * blockDim.x + threadIdx.x) >> 5;
    const int lane = threadIdx.x & 31;
    if (gw >= NCELLS) return;
    const int n = gw;
    const unsigned FULL = 0xffffffffu;
    const float* hr = g_h + (size_t)n * DMODEL;

    float v[24];
    float sum = 0.f;
#pragma unroll
    for (int k = 0; k < 24; k++) { v[k] = hr[lane + k * 32]; sum += v[k]; }
#pragma unroll
    for (int o = 16; o > 0; o >>= 1) sum += __shfl_xor_sync(FULL, sum, o);
    const float mu = sum * (1.0f / 768.0f);
    float var = 0.f;
#pragma unroll
    for (int k = 0; k < 24; k++) { float d = v[k] - mu; var += d * d; }
#pragma unroll
    for (int o = 16; o > 0; o >>= 1) var += __shfl_xor_sync(FULL, var, o);
    var *= (1.0f / 768.0f);
    const float r = rsqrtf(var + 1e-5f);

    bool anyv = false;
    if (lane < MAXH) anyv = (map[n * MAXH + lane] >= 0);
    anyv = __any_sync(FULL, anyv);

    const float* cr = g_cwp + (size_t)n * DMODEL;
#pragma unroll
    for (int k = 0; k < 24; k++) {
        int d = lane + k * 32;
        float val = (v[k] - mu) * r * gam[d] + bet[d];
        val = fmaxf(val, 0.f);
        out[(size_t)n * DMODEL + d] = anyv ? val : cr[d];
    }
}

// ---------------- launch ----------------------------------------------------
extern "C" void kernel_launch(void* const* d_in, const int* in_sizes, int n_in,
                              void* d_out, int out_size) {
    const float* cell   = (const float*)d_in[0];
    const float* hdr    = (const float*)d_in[1];
    const int*   map    = (const int*)  d_in[2];
    const int*   pos    = (const int*)  d_in[3];
    const float* inw    = (const float*)d_in[4];
    const float* inb    = (const float*)d_in[5];
    const float* outw   = (const float*)d_in[6];
    const float* outb   = (const float*)d_in[7];
    const float* rowe   = (const float*)d_in[8];
    const float* cole   = (const float*)d_in[9];
    const float* fusw   = (const float*)d_in[10];
    const float* fusb   = (const float*)d_in[11];
    const float* lng    = (const float*)d_in[12];
    const float* lnb    = (const float*)d_in[13];
    float* out  = (float*)d_out;
    float* wout = out + (size_t)NCELLS * DMODEL;

    float *cwp, *q, *ctx, *att, *h, *K, *V;
    __nv_bfloat16 *Ab, *Bb;
    cudaGetSymbolAddress((void**)&cwp, g_cwp);
    cudaGetSymbolAddress((void**)&q,   g_q);
    cudaGetSymbolAddress((void**)&ctx, g_ctx);
    cudaGetSymbolAddress((void**)&att, g_att);
    cudaGetSymbolAddress((void**)&h,   g_h);
    cudaGetSymbolAddress((void**)&K,   g_K);
    cudaGetSymbolAddress((void**)&V,   g_V);
    cudaGetSymbolAddress((void**)&Ab,  g_Abig);
    cudaGetSymbolAddress((void**)&Bb,  g_Bbig);

    const int MM_SMEM = MM_STAGES * MM_TB * 2;  // 128 KB
    cudaFuncSetAttribute(gemm_mma, cudaFuncAttributeMaxDynamicSharedMemorySize, MM_SMEM);

    // 1. cwp
    {
        int total = NCELLS * (DMODEL / 4);
        cwp_kernel<<<(total + 255) / 256, 256>>>(cell, pos, rowe, cole);
    }
    // 2. header K/V projections (512 rows, fp32 FFMA — tiny)
    {
        dim3 grid(NHDR / BM, DMODEL / BN);
        gemm_nt<<<grid, 256>>>(hdr, nullptr, inw + 768 * 768, 768, inb + 768,  K, NHDR);
        gemm_nt<<<grid, 256>>>(hdr, nullptr, inw + 2 * 768 * 768, 768, inb + 1536, V, NHDR);
    }
    dim3 mmgrid(NCELLS / 128, DMODEL / 128);
    // 3. Q projection (HMMA, split-bf16, K'=2304)
    {
        int tb = DMODEL * (768 / 4);
        splitB<<<(tb + 255) / 256, 256>>>(inw, 768, Bb);
        int ta = NCELLS * (768 / 4);
        splitA<<<(ta + 255) / 256, 256>>>(cwp, nullptr, 768, Ab);
        gemm_mma<<<mmgrid, 256, MM_SMEM>>>(Ab, Bb, inb, q, 2304);
    }
    // 4. attention
    attn_kernel<<<(NCELLS * 32 + 255) / 256, 256>>>(map, wout);
    // 5. out projection (HMMA)
    {
        int tb = DMODEL * (768 / 4);
        splitB<<<(tb + 255) / 256, 256>>>(outw, 768, Bb);
        int ta = NCELLS * (768 / 4);
        splitA<<<(ta + 255) / 256, 256>>>(ctx, nullptr, 768, Ab);
        gemm_mma<<<mmgrid, 256, MM_SMEM>>>(Ab, Bb, outb, att, 2304);
    }
    // 6. fusion: h = [cwp, att] @ fus_w^T + fus_b  (HMMA, K'=4608)
    {
        int tb = DMODEL * (1536 / 4);
        splitB<<<(tb + 255) / 256, 256>>>(fusw, 1536, Bb);
        int ta = NCELLS * (1536 / 4);
        splitA<<<(ta + 255) / 256, 256>>>(cwp, att, 1536, Ab);
        gemm_mma<<<mmgrid, 256, MM_SMEM>>>(Ab, Bb, fusb, h, 4608);
    }
    // 7. LayerNorm + ReLU + select
    ln_kernel<<<(NCELLS * 32 + 255) / 256, 256>>>(map, lng, lnb, out);
}